// round 3
// baseline (speedup 1.0000x reference)
#include <cuda_runtime.h>
#include <cuda_bf16.h>

#define BB 512
#define CC 3
#define TT 16384
#define NBLOCKS 1024
#define NTHREADS 256

// Deterministic partial-sum scratch (no device-side allocation allowed).
__device__ float g_ce[NBLOCKS];
__device__ float g_sq[NBLOCKS];
__device__ int   g_fl[NBLOCKS];

__device__ __forceinline__ int argmax3(float x0, float x1, float x2) {
    // First-occurrence-of-max semantics (matches jnp.argmax): strict >.
    int idx = 0; float best = x0;
    if (x1 > best) { best = x1; idx = 1; }
    if (x2 > best) { idx = 2; }
    return idx;
}

__global__ void __launch_bounds__(NTHREADS)
ce_main_kernel(const float* __restrict__ logits, const int* __restrict__ labels) {
    const int T4 = TT / 4;                      // 4096 chunks per row
    const int NCH = BB * T4;                    // 2,097,152 chunks total (fits int)

    float ce = 0.0f;
    float sq = 0.0f;
    int   fl = 0;

    const int stride = gridDim.x * blockDim.x;
    for (int ci = blockIdx.x * blockDim.x + threadIdx.x; ci < NCH; ci += stride) {
        const int t4 = ci & (T4 - 1);           // T4 is a power of two
        const int b  = ci >> 12;                // ci / 4096
        const int t  = t4 * 4;

        const float* p = logits + (long long)b * (CC * TT) + t;
        const float4 r0 = *reinterpret_cast<const float4*>(p);
        const float4 r1 = *reinterpret_cast<const float4*>(p + TT);
        const float4 r2 = *reinterpret_cast<const float4*>(p + 2 * TT);

        // labels: int32 (JAX demotes int64 -> int32 without x64), 4 per int4.
        const int4 q = *reinterpret_cast<const int4*>(labels + (long long)b * TT + t);

        float xa[4] = { r0.x, r0.y, r0.z, r0.w };
        float xb[4] = { r1.x, r1.y, r1.z, r1.w };
        float xc[4] = { r2.x, r2.y, r2.z, r2.w };
        int   lab[4] = { q.x, q.y, q.z, q.w };

        // Boundary values at t+4 (L1 hits: same/adjacent lines as neighbor thread's float4s)
        const bool has_next = (t + 4 < TT);
        float n0 = 0.f, n1 = 0.f, n2 = 0.f;
        if (has_next) {
            n0 = p[4];
            n1 = p[TT + 4];
            n2 = p[2 * TT + 4];
        }

        int pr[5];
        #pragma unroll
        for (int j = 0; j < 4; j++) {
            const float x0 = xa[j], x1 = xb[j], x2 = xc[j];
            // --- cross-entropy ---
            const float m  = fmaxf(x0, fmaxf(x1, x2));
            const float s  = __expf(x0 - m) + __expf(x1 - m) + __expf(x2 - m);
            const float lse = m + __logf(s);
            const int l = lab[j];
            const float xl = (l == 0) ? x0 : ((l == 1) ? x1 : x2);
            ce += lse - xl;
            // --- argmax for transition penalty ---
            pr[j] = argmax3(x0, x1, x2);
        }

        // --- smoothness: in-register diffs for j -> j+1 (j = 0..2) ---
        #pragma unroll
        for (int j = 0; j < 3; j++) {
            const float d0 = xa[j + 1] - xa[j];
            const float d1 = xb[j + 1] - xb[j];
            const float d2 = xc[j + 1] - xc[j];
            sq += d0 * d0 + d1 * d1 + d2 * d2;
        }
        if (has_next) {
            const float d0 = n0 - xa[3];
            const float d1 = n1 - xb[3];
            const float d2 = n2 - xc[3];
            sq += d0 * d0 + d1 * d1 + d2 * d2;
            pr[4] = argmax3(n0, n1, n2);
        }

        // --- transitions: bad iff next == (prev+2) mod 3, i.e. pair in {(0,2),(1,0),(2,1)}
        // bitmask over index prev*3+next: bits 2, 3, 7 -> 0x8C
        const int npairs = has_next ? 4 : 3;
        #pragma unroll
        for (int j = 0; j < 4; j++) {
            if (j < npairs) {
                fl |= (0x8C >> (pr[j] * 3 + pr[j + 1])) & 1;
            }
        }
    }

    // Deterministic block-tree reduction.
    __shared__ float sce[NTHREADS];
    __shared__ float ssq[NTHREADS];
    __shared__ int   sfl[NTHREADS];
    const int tid = threadIdx.x;
    sce[tid] = ce; ssq[tid] = sq; sfl[tid] = fl;
    __syncthreads();
    for (int s = NTHREADS / 2; s > 0; s >>= 1) {
        if (tid < s) {
            sce[tid] += sce[tid + s];
            ssq[tid] += ssq[tid + s];
            sfl[tid] |= sfl[tid + s];
        }
        __syncthreads();
    }
    if (tid == 0) {
        g_ce[blockIdx.x] = sce[0];
        g_sq[blockIdx.x] = ssq[0];
        g_fl[blockIdx.x] = sfl[0];
    }
}

__global__ void __launch_bounds__(NBLOCKS)
ce_final_kernel(float* __restrict__ out) {
    __shared__ float sce[NBLOCKS];
    __shared__ float ssq[NBLOCKS];
    __shared__ int   sfl[NBLOCKS];
    const int i = threadIdx.x;
    sce[i] = g_ce[i]; ssq[i] = g_sq[i]; sfl[i] = g_fl[i];
    __syncthreads();
    for (int s = NBLOCKS / 2; s > 0; s >>= 1) {
        if (i < s) {
            sce[i] += sce[i + s];
            ssq[i] += ssq[i + s];
            sfl[i] |= sfl[i + s];
        }
        __syncthreads();
    }
    if (i == 0) {
        const float ce_mean = sce[0] / (float)((long long)BB * TT);
        const float smooth  = 0.01f * (ssq[0] / (float)((long long)BB * CC * (TT - 1)));
        const float trans   = sfl[0] ? 0.1f : 0.0f;
        out[0] = ce_mean + smooth + trans;
    }
}

extern "C" void kernel_launch(void* const* d_in, const int* in_sizes, int n_in,
                              void* d_out, int out_size) {
    // Identify inputs by element count, independent of metadata order.
    const long long N_LOGITS = (long long)BB * CC * TT;  // 25,165,824
    const float* logits = nullptr;
    const int*   labels = nullptr;
    for (int i = 0; i < n_in; i++) {
        if (in_sizes[i] == (int)N_LOGITS) logits = (const float*)d_in[i];
        else                              labels = (const int*)d_in[i];
    }
    float* out = (float*)d_out;

    ce_main_kernel<<<NBLOCKS, NTHREADS>>>(logits, labels);
    ce_final_kernel<<<1, NBLOCKS>>>(out);
}